// round 7
// baseline (speedup 1.0000x reference)
#include <cuda_runtime.h>
#include <cuda_bf16.h>
#include <cstdint>

#define NB    4
#define NSEQ  512
#define DIMK  64
#define NCH   256
#define NT    1024

// device scratch
__device__ float d_M   [DIMK * NCH];
__device__ float d_Wq  [DIMK * NCH];
__device__ float d_Wk  [DIMK * NCH];
__device__ float d_cvec[NCH];
__device__ float d_qk1 [NB * NSEQ * NCH];
__device__ __nv_bfloat16 d_kk1b[NB * NSEQ * NCH];   // k@W1 in bf16
__device__ float d_v   [NB * NSEQ * DIMK];
// B operand (M matrix) bf16, [n][k] rows, XOR-swizzled 16B chunks
__device__ __align__(128) unsigned char d_Bhi[NCH * 128];

__device__ __forceinline__ uint32_t smem_to_u32(const void* p) {
    uint32_t a;
    asm("{ .reg .u64 t; cvta.to.shared.u64 t, %1; cvt.u32.u64 %0, t; }" : "=r"(a) : "l"(p));
    return a;
}
__device__ __forceinline__ void ldsm4(uint32_t& r0, uint32_t& r1, uint32_t& r2, uint32_t& r3, uint32_t addr) {
    asm volatile("ldmatrix.sync.aligned.m8n8.x4.shared.b16 {%0,%1,%2,%3}, [%4];"
                 : "=r"(r0), "=r"(r1), "=r"(r2), "=r"(r3) : "r"(addr));
}
__device__ __forceinline__ void mma16816(float* c, const uint32_t* a, uint32_t b0, uint32_t b1) {
    asm volatile("mma.sync.aligned.m16n8k16.row.col.f32.bf16.bf16.f32 "
                 "{%0,%1,%2,%3}, {%4,%5,%6,%7}, {%8,%9}, {%0,%1,%2,%3};"
                 : "+f"(c[0]), "+f"(c[1]), "+f"(c[2]), "+f"(c[3])
                 : "r"(a[0]), "r"(a[1]), "r"(a[2]), "r"(a[3]), "r"(b0), "r"(b1));
}
// swizzled byte offset for element (row, k) in a [row][64] bf16 tile, 128B rows
__device__ __forceinline__ unsigned swz(int row, int k) {
    return row * 128 + ((((k >> 3) ^ (row & 7))) << 4) + (k & 7) * 2;
}

// smem byte layout (pt_main)
#define OFF_A    32768      // A (p tile bf16) 16KB; Bhi at 0 (32KB)
#define OFF_EXT  49152
#define SMEM_TOTAL 66560    // 49152 + 4352*4
// ext float indices
#define E_QS    0
#define E_W2S   256
#define E_W1S   512
#define E_B1S   704
#define E_PJ    768
#define E_SIMS  1152
#define E_SPART 1664
#define E_GPART 2176
#define E_RPART 3200
#define E_GS    4224
#define E_RED   4288

// -------------------- K0a: fold weights --------------------
__global__ void prep_mats(const float* __restrict__ w_qkv, const float* __restrict__ pos_w2,
                          const float* __restrict__ pos_b2, const float* __restrict__ attn_w1,
                          const float* __restrict__ attn_b1) {
    int c = threadIdx.x, bid = blockIdx.x;
    if (bid == 192) {
        float acc = attn_b1[c];
        #pragma unroll 8
        for (int d = 0; d < DIMK; d++) acc = fmaf(pos_b2[d], attn_w1[d * NCH + c], acc);
        d_cvec[c] = acc;
        return;
    }
    int m = bid >> 6, k = bid & 63;
    const float* src = (m == 0) ? (pos_w2 + k * 64) : (m == 1) ? (w_qkv + k * 192) : (w_qkv + k * 192 + 64);
    float acc = 0.f;
    #pragma unroll 8
    for (int d = 0; d < DIMK; d++) acc = fmaf(src[d], attn_w1[d * NCH + c], acc);
    float* dst = (m == 0) ? d_M : (m == 1) ? d_Wq : d_Wk;
    dst[k * NCH + c] = acc;
}

// -------------------- K0a2: bf16 M in swizzled B layout --------------------
__global__ void prep_msplit() {
    int k = blockIdx.x, n = threadIdx.x;
    *(__nv_bfloat16*)(d_Bhi + swz(n, k)) = __float2bfloat16(d_M[k * NCH + n]);
}

// -------------------- K0b: projections --------------------
__global__ __launch_bounds__(256) void proj_kernel(const float* __restrict__ x,
                                                   const float* __restrict__ w_qkv) {
    __shared__ float xs[16][64];
    int c = threadIdx.x;
    int row0 = blockIdx.x * 16;
    for (int idx = c; idx < 16 * 64; idx += 256) xs[idx >> 6][idx & 63] = x[row0 * 64 + idx];
    __syncthreads();
    float accq[16], acck[16];
    #pragma unroll
    for (int r = 0; r < 16; r++) { accq[r] = 0.f; acck[r] = 0.f; }
    for (int k = 0; k < 64; k++) {
        float wq = d_Wq[k * NCH + c], wk = d_Wk[k * NCH + c];
        #pragma unroll
        for (int r = 0; r < 16; r++) {
            float xv = xs[r][k];
            accq[r] = fmaf(xv, wq, accq[r]);
            acck[r] = fmaf(xv, wk, acck[r]);
        }
    }
    float cv = d_cvec[c];
    #pragma unroll
    for (int r = 0; r < 16; r++) {
        d_qk1[(size_t)(row0 + r) * NCH + c] = accq[r] + cv;
        d_kk1b[(size_t)(row0 + r) * NCH + c] = __float2bfloat16(acck[r]);
    }
    int d = c & 63, rg = c >> 6;
    for (int r = rg; r < 16; r += 4) {
        float acc = 0.f;
        #pragma unroll 8
        for (int k = 0; k < 64; k++) acc = fmaf(xs[r][k], w_qkv[k * 192 + 128 + d], acc);
        d_v[(size_t)(row0 + r) * 64 + d] = acc;
    }
}

// -------------------- K1: fused attention (32 warps, M16N64 tiles, bf16 kk1) ---------
__global__ __launch_bounds__(NT, 1) void pt_main(const float* __restrict__ pos,
                                                 const float* __restrict__ pos_w1,
                                                 const float* __restrict__ pos_b1,
                                                 const float* __restrict__ pos_w2,
                                                 const float* __restrict__ pos_b2,
                                                 const float* __restrict__ attn_w2,
                                                 float* __restrict__ out) {
    extern __shared__ __align__(1024) char smc[];
    float* ext = (float*)(smc + OFF_EXT);
    float* qs = ext + E_QS; float* w2s = ext + E_W2S; float* w1s = ext + E_W1S;
    float* b1s = ext + E_B1S; float* pj = ext + E_PJ; float* sims = ext + E_SIMS;
    float* spart = ext + E_SPART; float* gpart = ext + E_GPART; float* rpart = ext + E_RPART;
    float* gs = ext + E_GS; float* red = ext + E_RED;

    uint32_t sbase = smem_to_u32(smc);
    int tid = threadIdx.x, wid = tid >> 5, lane = tid & 31;
    int bi = blockIdx.x, b = bi >> 9;

    // stage B (32 KB)
    {
        float4* dh = (float4*)smc;
        const float4* sh = (const float4*)d_Bhi;
        for (int idx = tid; idx < 2048; idx += NT) dh[idx] = sh[idx];
    }
    if (tid < 256)      { qs[tid] = d_qk1[(size_t)bi * NCH + tid]; w2s[tid] = attn_w2[tid]; }
    else if (tid < 448) { w1s[tid - 256] = pos_w1[tid - 256]; }
    else if (tid < 512) { b1s[tid - 448] = pos_b1[tid - 448]; }
    float px = pos[bi * 3 + 0], py = pos[bi * 3 + 1], pz = pos[bi * 3 + 2];
    __syncthreads();

    // warp tiling: mg = m-group (16 rows, 8 groups), ng = n-group (64 cols, 4 groups)
    int mg = wid >> 2, ng = wid & 3;
    int m0 = mg * 16, n0base = ng * 64;
    int r8 = lane & 7, g = lane >> 3;
    int rowAoff = (g & 1) << 3, kcA = g >> 1;
    int nBoff = (g >> 1) << 3, kcB = g & 1;
    int rq = lane >> 2, t4 = lane & 3;

    // ---------------- PASS 1 ----------------
    for (int t = 0; t < 4; t++) {
        if (tid < 384) {
            int j = tid & 127, d = tid >> 7;
            pj[d * 128 + j] = pos[((size_t)b * NSEQ + t * 128 + j) * 3 + d];
        }
        __syncthreads();
        // p tile -> bf16, packed pair stores
        char* Ah = smc + OFF_A;
        for (int idx = tid; idx < 4096; idx += NT) {
            int j = idx >> 5, k = (idx & 31) << 1;
            float rx = px - pj[j], ry = py - pj[128 + j], rz = pz - pj[256 + j];
            float v0 = fmaf(rx, w1s[k],     fmaf(ry, w1s[64 + k],     fmaf(rz, w1s[128 + k],     b1s[k])));
            float v1 = fmaf(rx, w1s[k + 1], fmaf(ry, w1s[64 + k + 1], fmaf(rz, w1s[128 + k + 1], b1s[k + 1])));
            __nv_bfloat162 hh = __floats2bfloat162_rn(fmaxf(v0, 0.f), fmaxf(v1, 0.f));
            unsigned sw = j * 128 + ((((k >> 3) ^ (j & 7))) << 4) + (k & 7) * 2;
            *(uint32_t*)(Ah + sw) = *(uint32_t*)&hh;
        }
        __syncthreads();

        uint32_t Abase = sbase + OFF_A + (m0 + rowAoff + r8) * 128;
        const __nv_bfloat16* kkT = d_kk1b + ((size_t)((b << 9) + t * 128 + m0 + rq)) * NCH;
        float sm0 = 0.f, sm1 = 0.f;

        #pragma unroll
        for (int ch = 0; ch < 2; ch++) {
            int n0 = n0base + ch * 32;
            // prefetch bf16 kk1 packed: [rowhalf][n8]
            uint32_t kku[2][4];
            #pragma unroll
            for (int n8 = 0; n8 < 4; n8++) {
                int n = n0 + n8 * 8 + t4 * 2;
                kku[0][n8] = *(const uint32_t*)(kkT + n);
                kku[1][n8] = *(const uint32_t*)(kkT + 8 * NCH + n);
            }
            float acc[4][4];
            #pragma unroll
            for (int q = 0; q < 4; q++)
                #pragma unroll
                for (int r = 0; r < 4; r++) acc[q][r] = 0.f;

            #pragma unroll
            for (int ks = 0; ks < 4; ks++) {
                uint32_t bh[2][4];
                uint32_t bxor = (uint32_t)(((2 * ks + kcB) ^ r8) << 4);
                #pragma unroll
                for (int nb = 0; nb < 2; nb++) {
                    uint32_t baddr = sbase + (n0 + nb * 16 + nBoff + r8) * 128 + bxor;
                    ldsm4(bh[nb][0], bh[nb][1], bh[nb][2], bh[nb][3], baddr);
                }
                uint32_t ah[4];
                uint32_t axor = (uint32_t)(((2 * ks + kcA) ^ r8) << 4);
                ldsm4(ah[0], ah[1], ah[2], ah[3], Abase + axor);
                #pragma unroll
                for (int nb = 0; nb < 2; nb++) {
                    mma16816(acc[2 * nb],     ah, bh[nb][0], bh[nb][1]);
                    mma16816(acc[2 * nb + 1], ah, bh[nb][2], bh[nb][3]);
                }
            }
            // epilogue for this 32-col chunk
            float s0 = 0.f, s1 = 0.f;
            #pragma unroll
            for (int n8 = 0; n8 < 4; n8++) {
                int n = n0 + n8 * 8 + t4 * 2;
                float2 qv = *(const float2*)(qs + n);
                float2 wv = *(const float2*)(w2s + n);
                float2 k0 = __bfloat1622float2(*(const __nv_bfloat162*)&kku[0][n8]);
                float2 k1 = __bfloat1622float2(*(const __nv_bfloat162*)&kku[1][n8]);
                s0 = fmaf(fmaxf(acc[n8][0] + qv.x - k0.x, 0.f), wv.x,
                     fmaf(fmaxf(acc[n8][1] + qv.y - k0.y, 0.f), wv.y, s0));
                s1 = fmaf(fmaxf(acc[n8][2] + qv.x - k1.x, 0.f), wv.x,
                     fmaf(fmaxf(acc[n8][3] + qv.y - k1.y, 0.f), wv.y, s1));
            }
            sm0 += s0; sm1 += s1;
        }
        // quad reduce + write partials
        sm0 += __shfl_xor_sync(0xffffffffu, sm0, 1); sm0 += __shfl_xor_sync(0xffffffffu, sm0, 2);
        sm1 += __shfl_xor_sync(0xffffffffu, sm1, 1); sm1 += __shfl_xor_sync(0xffffffffu, sm1, 2);
        if (t4 == 0) {
            spart[ng * 128 + m0 + rq]     = sm0;
            spart[ng * 128 + m0 + rq + 8] = sm1;
        }
        __syncthreads();
        if (tid < 128) sims[t * 128 + tid] = spart[tid] + spart[128 + tid] + spart[256 + tid] + spart[384 + tid];
        __syncthreads();
    }

    // ---------------- softmax over 512 sims (threads 0..511 active) ----------------
    {
        float s = 0.f, e = 0.f;
        if (tid < 512) {
            s = sims[tid];
            float m = s;
            #pragma unroll
            for (int off = 16; off; off >>= 1) m = fmaxf(m, __shfl_xor_sync(0xffffffffu, m, off));
            if (lane == 0) red[wid] = m;
        }
        __syncthreads();
        if (tid < 32) {
            float v = (tid < 16) ? red[tid] : -3.4e38f;
            #pragma unroll
            for (int off = 8; off; off >>= 1) v = fmaxf(v, __shfl_xor_sync(0xffffffffu, v, off));
            if (tid == 0) red[32] = v;
        }
        __syncthreads();
        if (tid < 512) {
            e = __expf(s - red[32]);
            float tt = e;
            #pragma unroll
            for (int off = 16; off; off >>= 1) tt += __shfl_xor_sync(0xffffffffu, tt, off);
            if (lane == 0) red[wid] = tt;
        }
        __syncthreads();
        if (tid < 32) {
            float v = (tid < 16) ? red[tid] : 0.f;
            #pragma unroll
            for (int off = 8; off; off >>= 1) v += __shfl_xor_sync(0xffffffffu, v, off);
            if (tid == 0) red[33] = v;
        }
        __syncthreads();
        if (tid < 512) sims[tid] = e / red[33];
        __syncthreads();
    }

    // ---------------- PASS 2: recompute p fp32; g = a@p, r = a@v ----------------
    {
        float* ps = (float*)smc;   // [128][64] fp32, reuses B region (dead now)
        int k = tid & 63, jg = tid >> 6;   // 16 j-groups of 8 rows
        float gacc = 0.f, racc = 0.f;
        for (int t = 0; t < 4; t++) {
            if (tid < 384) {
                int j = tid & 127, d = tid >> 7;
                pj[d * 128 + j] = pos[((size_t)b * NSEQ + t * 128 + j) * 3 + d];
            }
            __syncthreads();
            for (int idx = tid; idx < 8192; idx += NT) {
                int j = idx >> 6, kk = idx & 63;
                float rx = px - pj[j], ry = py - pj[128 + j], rz = pz - pj[256 + j];
                float v = fmaf(rx, w1s[kk], fmaf(ry, w1s[64 + kk], fmaf(rz, w1s[128 + kk], b1s[kk])));
                ps[j * 64 + kk] = fmaxf(v, 0.f);
            }
            __syncthreads();
            #pragma unroll
            for (int jj = 0; jj < 8; jj++) {
                int jl = jg * 8 + jj;
                int j = t * 128 + jl;
                float a = sims[j];
                gacc = fmaf(a, ps[jl * 64 + k], gacc);
                racc = fmaf(a, d_v[((size_t)(b << 9) + j) * 64 + k], racc);
            }
            __syncthreads();
        }
        gpart[tid] = gacc;
        rpart[tid] = racc;
        __syncthreads();
        float rsum = 0.f;
        if (tid < 64) {
            float gsum = 0.f;
            #pragma unroll
            for (int w = 0; w < 16; w++) { gsum += gpart[w * 64 + tid]; rsum += rpart[w * 64 + tid]; }
            gs[tid] = gsum;
        }
        __syncthreads();
        if (tid < 64) {
            float o = rsum + pos_b2[tid];
            #pragma unroll 8
            for (int kk = 0; kk < 64; kk++) o = fmaf(gs[kk], pos_w2[kk * 64 + tid], o);
            out[(size_t)bi * 64 + tid] = o;
        }
    }
}

// -------------------- launch --------------------
extern "C" void kernel_launch(void* const* d_in, const int* in_sizes, int n_in,
                              void* d_out, int out_size) {
    const float* x       = (const float*)d_in[0];
    const float* pos     = (const float*)d_in[1];
    const float* w_qkv   = (const float*)d_in[2];
    const float* pos_w1  = (const float*)d_in[3];
    const float* pos_b1  = (const float*)d_in[4];
    const float* pos_w2  = (const float*)d_in[5];
    const float* pos_b2  = (const float*)d_in[6];
    const float* attn_w1 = (const float*)d_in[7];
    const float* attn_b1 = (const float*)d_in[8];
    const float* attn_w2 = (const float*)d_in[9];
    // attn_b2 (d_in[10]) cancels in softmax
    float* out = (float*)d_out;

    cudaFuncSetAttribute(pt_main, cudaFuncAttributeMaxDynamicSharedMemorySize, SMEM_TOTAL);

    prep_mats<<<193, 256>>>(w_qkv, pos_w2, pos_b2, attn_w1, attn_b1);
    prep_msplit<<<64, 256>>>();
    proj_kernel<<<128, 256>>>(x, w_qkv);
    pt_main<<<NB * NSEQ, NT, SMEM_TOTAL>>>(pos, pos_w1, pos_b1, pos_w2, pos_b2, attn_w2, out);
}

// round 8
// speedup vs baseline: 1.1328x; 1.1328x over previous
#include <cuda_runtime.h>
#include <cuda_bf16.h>
#include <cstdint>

#define NB    4
#define NSEQ  512
#define DIMK  64
#define NCH   256
#define NT    512

// device scratch
__device__ float d_M   [DIMK * NCH];
__device__ float d_Wq  [DIMK * NCH];
__device__ float d_Wk  [DIMK * NCH];
__device__ float d_cvec[NCH];
__device__ float d_qk1 [NB * NSEQ * NCH];
__device__ __nv_bfloat16 d_kk1b[NB * NSEQ * NCH];   // k@W1 in bf16
__device__ float d_v   [NB * NSEQ * DIMK];
// B operand (M matrix) bf16, [n][k] rows, XOR-swizzled 16B chunks
__device__ __align__(128) unsigned char d_Bhi[NCH * 128];

__device__ __forceinline__ uint32_t smem_to_u32(const void* p) {
    uint32_t a;
    asm("{ .reg .u64 t; cvta.to.shared.u64 t, %1; cvt.u32.u64 %0, t; }" : "=r"(a) : "l"(p));
    return a;
}
__device__ __forceinline__ void ldsm4(uint32_t& r0, uint32_t& r1, uint32_t& r2, uint32_t& r3, uint32_t addr) {
    asm volatile("ldmatrix.sync.aligned.m8n8.x4.shared.b16 {%0,%1,%2,%3}, [%4];"
                 : "=r"(r0), "=r"(r1), "=r"(r2), "=r"(r3) : "r"(addr));
}
__device__ __forceinline__ void mma16816(float* c, const uint32_t* a, uint32_t b0, uint32_t b1) {
    asm volatile("mma.sync.aligned.m16n8k16.row.col.f32.bf16.bf16.f32 "
                 "{%0,%1,%2,%3}, {%4,%5,%6,%7}, {%8,%9}, {%0,%1,%2,%3};"
                 : "+f"(c[0]), "+f"(c[1]), "+f"(c[2]), "+f"(c[3])
                 : "r"(a[0]), "r"(a[1]), "r"(a[2]), "r"(a[3]), "r"(b0), "r"(b1));
}
// swizzled byte offset for element (row, k) in a [row][64] bf16 tile, 128B rows
__device__ __forceinline__ unsigned swz(int row, int k) {
    return row * 128 + ((((k >> 3) ^ (row & 7))) << 4) + (k & 7) * 2;
}

// smem byte layout (pt_main): B staged at 0..32KB (dead after init ldsm),
// A tile (16KB) reuses bytes 0..16KB afterwards. ext floats at 32KB.
#define OFF_EXT  32768
#define SMEM_TOTAL 51200    // 32768 + 4608*4
// ext float indices
#define E_PJ    0        // 1536: pos_all [3][512]
#define E_QS    1536     // 256
#define E_W2S   1792     // 256
#define E_W1S   2048     // 192
#define E_B1S   2240     // 64
#define E_SIMS  2304     // 512
#define E_SPART 2816     // 512
#define E_GPART 3328     // 512
#define E_RPART 3840     // 512
#define E_GS    4352     // 64
#define E_RED   4416     // 64

// -------------------- K0a: fold weights --------------------
__global__ void prep_mats(const float* __restrict__ w_qkv, const float* __restrict__ pos_w2,
                          const float* __restrict__ pos_b2, const float* __restrict__ attn_w1,
                          const float* __restrict__ attn_b1) {
    int c = threadIdx.x, bid = blockIdx.x;
    if (bid == 192) {
        float acc = attn_b1[c];
        #pragma unroll 8
        for (int d = 0; d < DIMK; d++) acc = fmaf(pos_b2[d], attn_w1[d * NCH + c], acc);
        d_cvec[c] = acc;
        return;
    }
    int m = bid >> 6, k = bid & 63;
    const float* src = (m == 0) ? (pos_w2 + k * 64) : (m == 1) ? (w_qkv + k * 192) : (w_qkv + k * 192 + 64);
    float acc = 0.f;
    #pragma unroll 8
    for (int d = 0; d < DIMK; d++) acc = fmaf(src[d], attn_w1[d * NCH + c], acc);
    float* dst = (m == 0) ? d_M : (m == 1) ? d_Wq : d_Wk;
    dst[k * NCH + c] = acc;
}

// -------------------- K0a2: bf16 M in swizzled B layout --------------------
__global__ void prep_msplit() {
    int k = blockIdx.x, n = threadIdx.x;
    *(__nv_bfloat16*)(d_Bhi + swz(n, k)) = __float2bfloat16(d_M[k * NCH + n]);
}

// -------------------- K0b: projections --------------------
__global__ __launch_bounds__(256) void proj_kernel(const float* __restrict__ x,
                                                   const float* __restrict__ w_qkv) {
    __shared__ float xs[16][64];
    int c = threadIdx.x;
    int row0 = blockIdx.x * 16;
    for (int idx = c; idx < 16 * 64; idx += 256) xs[idx >> 6][idx & 63] = x[row0 * 64 + idx];
    __syncthreads();
    float accq[16], acck[16];
    #pragma unroll
    for (int r = 0; r < 16; r++) { accq[r] = 0.f; acck[r] = 0.f; }
    for (int k = 0; k < 64; k++) {
        float wq = d_Wq[k * NCH + c], wk = d_Wk[k * NCH + c];
        #pragma unroll
        for (int r = 0; r < 16; r++) {
            float xv = xs[r][k];
            accq[r] = fmaf(xv, wq, accq[r]);
            acck[r] = fmaf(xv, wk, acck[r]);
        }
    }
    float cv = d_cvec[c];
    #pragma unroll
    for (int r = 0; r < 16; r++) {
        d_qk1[(size_t)(row0 + r) * NCH + c] = accq[r] + cv;
        d_kk1b[(size_t)(row0 + r) * NCH + c] = __float2bfloat16(acck[r]);
    }
    int d = c & 63, rg = c >> 6;
    for (int r = rg; r < 16; r += 4) {
        float acc = 0.f;
        #pragma unroll 8
        for (int k = 0; k < 64; k++) acc = fmaf(xs[r][k], w_qkv[k * 192 + 128 + d], acc);
        d_v[(size_t)(row0 + r) * 64 + d] = acc;
    }
}

// -------------------- K1: fused attention (B held in registers) --------------------
__global__ __launch_bounds__(NT, 1) void pt_main(const float* __restrict__ pos,
                                                 const float* __restrict__ pos_w1,
                                                 const float* __restrict__ pos_b1,
                                                 const float* __restrict__ pos_w2,
                                                 const float* __restrict__ pos_b2,
                                                 const float* __restrict__ attn_w2,
                                                 float* __restrict__ out) {
    extern __shared__ __align__(1024) char smc[];
    float* ext = (float*)(smc + OFF_EXT);
    float* pjall = ext + E_PJ; float* qs = ext + E_QS; float* w2s = ext + E_W2S;
    float* w1s = ext + E_W1S; float* b1s = ext + E_B1S; float* sims = ext + E_SIMS;
    float* spart = ext + E_SPART; float* gpart = ext + E_GPART; float* rpart = ext + E_RPART;
    float* gs = ext + E_GS; float* red = ext + E_RED;

    uint32_t sbase = smem_to_u32(smc);
    int tid = threadIdx.x, wid = tid >> 5, lane = tid & 31;
    int bi = blockIdx.x, b = bi >> 9;

    // stage B (32 KB) + block-invariant data + all pos_j
    {
        float4* dh = (float4*)smc;
        const float4* sh = (const float4*)d_Bhi;
        for (int idx = tid; idx < 2048; idx += NT) dh[idx] = sh[idx];
    }
    for (int idx = tid; idx < 1536; idx += NT) {
        int d = idx >> 9, j = idx & 511;
        pjall[d * 512 + j] = pos[((size_t)b * NSEQ + j) * 3 + d];
    }
    if (tid < 256)      { qs[tid] = d_qk1[(size_t)bi * NCH + tid]; w2s[tid] = attn_w2[tid]; }
    else if (tid < 448) { w1s[tid - 256] = pos_w1[tid - 256]; }
    else                { b1s[tid - 448] = pos_b1[tid - 448]; }
    float px = pos[bi * 3 + 0], py = pos[bi * 3 + 1], pz = pos[bi * 3 + 2];
    __syncthreads();

    // warp tiling: mg = m-group (32 rows, 4 groups), ng = n-group (64 cols, 4 groups)
    int mg = wid >> 2, ng = wid & 3;
    int m0 = mg * 32, n0base = ng * 64;
    int r8 = lane & 7, g = lane >> 3;
    int rowAoff = (g & 1) << 3, kcA = g >> 1;
    int nBoff = (g >> 1) << 3, kcB = g & 1;
    int rq = lane >> 2, t4 = lane & 3;

    // load B into registers ONCE: Breg[ch][nb][ks][4]
    uint32_t Breg[2][2][4][4];
    #pragma unroll
    for (int ch = 0; ch < 2; ch++)
        #pragma unroll
        for (int nb = 0; nb < 2; nb++)
            #pragma unroll
            for (int ks = 0; ks < 4; ks++) {
                uint32_t baddr = sbase + (n0base + ch * 32 + nb * 16 + nBoff + r8) * 128
                               + (uint32_t)(((2 * ks + kcB) ^ r8) << 4);
                ldsm4(Breg[ch][nb][ks][0], Breg[ch][nb][ks][1],
                      Breg[ch][nb][ks][2], Breg[ch][nb][ks][3], baddr);
            }
    __syncthreads();   // B smem region now dead; A tile reuses bytes 0..16KB

    // ---------------- PASS 1 ----------------
    for (int t = 0; t < 4; t++) {
        // p tile -> bf16 into A (bytes 0..16KB), packed pair stores
        for (int idx = tid; idx < 4096; idx += NT) {
            int j = idx >> 5, k = (idx & 31) << 1;
            int jg = t * 128 + j;
            float rx = px - pjall[jg], ry = py - pjall[512 + jg], rz = pz - pjall[1024 + jg];
            float v0 = fmaf(rx, w1s[k],     fmaf(ry, w1s[64 + k],     fmaf(rz, w1s[128 + k],     b1s[k])));
            float v1 = fmaf(rx, w1s[k + 1], fmaf(ry, w1s[64 + k + 1], fmaf(rz, w1s[128 + k + 1], b1s[k + 1])));
            __nv_bfloat162 hh = __floats2bfloat162_rn(fmaxf(v0, 0.f), fmaxf(v1, 0.f));
            unsigned sw = j * 128 + ((((k >> 3) ^ (j & 7))) << 4) + (k & 7) * 2;
            *(uint32_t*)(smc + sw) = *(uint32_t*)&hh;
        }
        __syncthreads();

        uint32_t Abase = sbase + (m0 + rowAoff + r8) * 128;
        const __nv_bfloat16* kkT = d_kk1b + ((size_t)((b << 9) + t * 128 + m0 + rq)) * NCH;
        float sm[4] = {0.f, 0.f, 0.f, 0.f};

        #pragma unroll
        for (int ch = 0; ch < 2; ch++) {
            int n0 = n0base + ch * 32;
            float acc[2][4][4];
            #pragma unroll
            for (int i = 0; i < 2; i++)
                #pragma unroll
                for (int q = 0; q < 4; q++)
                    #pragma unroll
                    for (int r = 0; r < 4; r++) acc[i][q][r] = 0.f;

            #pragma unroll
            for (int ks = 0; ks < 4; ks++) {
                uint32_t axor = (uint32_t)(((2 * ks + kcA) ^ r8) << 4);
                #pragma unroll
                for (int mb = 0; mb < 2; mb++) {
                    uint32_t ah[4];
                    ldsm4(ah[0], ah[1], ah[2], ah[3], Abase + mb * 2048 + axor);
                    #pragma unroll
                    for (int nb = 0; nb < 2; nb++) {
                        mma16816(acc[mb][2 * nb],     ah, Breg[ch][nb][ks][0], Breg[ch][nb][ks][1]);
                        mma16816(acc[mb][2 * nb + 1], ah, Breg[ch][nb][ks][2], Breg[ch][nb][ks][3]);
                    }
                }
            }
            // epilogue for this 32-col chunk (4 row-slots: rq, rq+8, rq+16, rq+24)
            #pragma unroll
            for (int mb = 0; mb < 2; mb++) {
                float s0 = 0.f, s1 = 0.f;
                const __nv_bfloat16* kkm = kkT + mb * 16 * NCH;
                #pragma unroll
                for (int n8 = 0; n8 < 4; n8++) {
                    int n = n0 + n8 * 8 + t4 * 2;
                    float2 qv = *(const float2*)(qs + n);
                    float2 wv = *(const float2*)(w2s + n);
                    float2 k0 = __bfloat1622float2(*(const __nv_bfloat162*)(kkm + n));
                    float2 k1 = __bfloat1622float2(*(const __nv_bfloat162*)(kkm + 8 * NCH + n));
                    s0 = fmaf(fmaxf(acc[mb][n8][0] + qv.x - k0.x, 0.f), wv.x,
                         fmaf(fmaxf(acc[mb][n8][1] + qv.y - k0.y, 0.f), wv.y, s0));
                    s1 = fmaf(fmaxf(acc[mb][n8][2] + qv.x - k1.x, 0.f), wv.x,
                         fmaf(fmaxf(acc[mb][n8][3] + qv.y - k1.y, 0.f), wv.y, s1));
                }
                sm[2 * mb] += s0; sm[2 * mb + 1] += s1;
            }
        }
        // quad reduce + write partials
        #pragma unroll
        for (int q = 0; q < 4; q++) {
            sm[q] += __shfl_xor_sync(0xffffffffu, sm[q], 1);
            sm[q] += __shfl_xor_sync(0xffffffffu, sm[q], 2);
        }
        if (t4 == 0) {
            spart[ng * 128 + m0 + rq]      = sm[0];
            spart[ng * 128 + m0 + rq + 8]  = sm[1];
            spart[ng * 128 + m0 + rq + 16] = sm[2];
            spart[ng * 128 + m0 + rq + 24] = sm[3];
        }
        __syncthreads();
        if (tid < 128) sims[t * 128 + tid] = spart[tid] + spart[128 + tid] + spart[256 + tid] + spart[384 + tid];
        __syncthreads();
    }

    // ---------------- softmax over 512 sims ----------------
    {
        float s = sims[tid];
        float m = s;
        #pragma unroll
        for (int off = 16; off; off >>= 1) m = fmaxf(m, __shfl_xor_sync(0xffffffffu, m, off));
        if (lane == 0) red[wid] = m;
        __syncthreads();
        if (tid < 32) {
            float v = (tid < 16) ? red[tid] : -3.4e38f;
            #pragma unroll
            for (int off = 8; off; off >>= 1) v = fmaxf(v, __shfl_xor_sync(0xffffffffu, v, off));
            if (tid == 0) red[32] = v;
        }
        __syncthreads();
        float e = __expf(s - red[32]);
        float tt = e;
        #pragma unroll
        for (int off = 16; off; off >>= 1) tt += __shfl_xor_sync(0xffffffffu, tt, off);
        if (lane == 0) red[wid] = tt;
        __syncthreads();
        if (tid < 32) {
            float v = (tid < 16) ? red[tid] : 0.f;
            #pragma unroll
            for (int off = 8; off; off >>= 1) v += __shfl_xor_sync(0xffffffffu, v, off);
            if (tid == 0) red[33] = v;
        }
        __syncthreads();
        sims[tid] = e / red[33];
        __syncthreads();
    }

    // ---------------- PASS 2: per-thread p recompute; g = a@p, r = a@v ----------------
    {
        int k = tid & 63, jg = tid >> 6;     // 8 j-groups of 64 rows
        float w0 = w1s[k], w1c = w1s[64 + k], w2c = w1s[128 + k], bb = b1s[k];
        float gacc = 0.f, racc = 0.f;
        const float* vb = d_v + ((size_t)(b << 9) + jg * 64) * 64 + k;
        int j0 = jg * 64;
        #pragma unroll 4
        for (int jj = 0; jj < 64; jj++) {
            int j = j0 + jj;
            float a = sims[j];
            float rx = px - pjall[j], ry = py - pjall[512 + j], rz = pz - pjall[1024 + j];
            float pv = fmaxf(fmaf(rx, w0, fmaf(ry, w1c, fmaf(rz, w2c, bb))), 0.f);
            gacc = fmaf(a, pv, gacc);
            racc = fmaf(a, vb[jj * 64], racc);
        }
        gpart[tid] = gacc;
        rpart[tid] = racc;
        __syncthreads();
        float rsum = 0.f;
        if (tid < 64) {
            float gsum = 0.f;
            #pragma unroll
            for (int w = 0; w < 8; w++) { gsum += gpart[w * 64 + tid]; rsum += rpart[w * 64 + tid]; }
            gs[tid] = gsum;
        }
        __syncthreads();
        if (tid < 64) {
            float o = rsum + pos_b2[tid];
            #pragma unroll 8
            for (int kk = 0; kk < 64; kk++) o = fmaf(gs[kk], pos_w2[kk * 64 + tid], o);
            out[(size_t)bi * 64 + tid] = o;
        }
    }
}

// -------------------- launch --------------------
extern "C" void kernel_launch(void* const* d_in, const int* in_sizes, int n_in,
                              void* d_out, int out_size) {
    const float* x       = (const float*)d_in[0];
    const float* pos     = (const float*)d_in[1];
    const float* w_qkv   = (const float*)d_in[2];
    const float* pos_w1  = (const float*)d_in[3];
    const float* pos_b1  = (const float*)d_in[4];
    const float* pos_w2  = (const float*)d_in[5];
    const float* pos_b2  = (const float*)d_in[6];
    const float* attn_w1 = (const float*)d_in[7];
    const float* attn_b1 = (const float*)d_in[8];
    const float* attn_w2 = (const float*)d_in[9];
    // attn_b2 (d_in[10]) cancels in softmax
    float* out = (float*)d_out;

    cudaFuncSetAttribute(pt_main, cudaFuncAttributeMaxDynamicSharedMemorySize, SMEM_TOTAL);

    prep_mats<<<193, 256>>>(w_qkv, pos_w2, pos_b2, attn_w1, attn_b1);
    prep_msplit<<<64, 256>>>();
    proj_kernel<<<128, 256>>>(x, w_qkv);
    pt_main<<<NB * NSEQ, NT, SMEM_TOTAL>>>(pos, pos_w1, pos_b1, pos_w2, pos_b2, attn_w2, out);
}

// round 9
// speedup vs baseline: 1.2628x; 1.1148x over previous
#include <cuda_runtime.h>
#include <cuda_bf16.h>
#include <cstdint>

#define NB    4
#define NSEQ  512
#define DIMK  64
#define NCH   256
#define NT    512

// device scratch
__device__ float d_M   [DIMK * NCH];
__device__ float d_Wq  [DIMK * NCH];
__device__ float d_Wk  [DIMK * NCH];
__device__ float d_cvec[NCH];
__device__ float d_qk1 [NB * NSEQ * NCH];
__device__ __nv_bfloat16 d_kk1b[NB * NSEQ * NCH];   // k@W1 in bf16
__device__ float d_v   [NB * NSEQ * DIMK];
// B operand (M matrix) bf16, [n][k] rows, XOR-swizzled 16B chunks
__device__ __align__(128) unsigned char d_Bhi[NCH * 128];

__device__ __forceinline__ uint32_t smem_to_u32(const void* p) {
    uint32_t a;
    asm("{ .reg .u64 t; cvta.to.shared.u64 t, %1; cvt.u32.u64 %0, t; }" : "=r"(a) : "l"(p));
    return a;
}
__device__ __forceinline__ void ldsm4(uint32_t& r0, uint32_t& r1, uint32_t& r2, uint32_t& r3, uint32_t addr) {
    asm volatile("ldmatrix.sync.aligned.m8n8.x4.shared.b16 {%0,%1,%2,%3}, [%4];"
                 : "=r"(r0), "=r"(r1), "=r"(r2), "=r"(r3) : "r"(addr));
}
__device__ __forceinline__ void mma16816(float* c, const uint32_t* a, uint32_t b0, uint32_t b1) {
    asm volatile("mma.sync.aligned.m16n8k16.row.col.f32.bf16.bf16.f32 "
                 "{%0,%1,%2,%3}, {%4,%5,%6,%7}, {%8,%9}, {%0,%1,%2,%3};"
                 : "+f"(c[0]), "+f"(c[1]), "+f"(c[2]), "+f"(c[3])
                 : "r"(a[0]), "r"(a[1]), "r"(a[2]), "r"(a[3]), "r"(b0), "r"(b1));
}
// swizzled byte offset for element (row, k), 128B rows
__device__ __forceinline__ unsigned swz(int row, int k) {
    return row * 128 + ((((k >> 3) ^ (row & 7))) << 4) + (k & 7) * 2;
}

// smem byte layout (pt_main): B staged at 0..32KB (dead after init ldsm);
// full A (p bf16 [512][64], swizzled 128B rows) = 64KB at 0..65536; ext after.
#define OFF_EXT  65536
#define SMEM_TOTAL 89600    // 65536 + 6016*4
// ext float indices
#define E_PJ    0        // 1536: pos_all [3][512]
#define E_QS    1536     // 256
#define E_W2S   1792     // 256
#define E_W1S   2048     // 192
#define E_B1S   2240     // 64
#define E_SIMS  2304     // 512
#define E_SPART 2816     // 2048: [4 ng][512]
#define E_GPART 4864     // 512
#define E_RPART 5376     // 512
#define E_GS    5888     // 64
#define E_RED   5952     // 64

// -------------------- K0a: fold weights --------------------
__global__ void prep_mats(const float* __restrict__ w_qkv, const float* __restrict__ pos_w2,
                          const float* __restrict__ pos_b2, const float* __restrict__ attn_w1,
                          const float* __restrict__ attn_b1) {
    int c = threadIdx.x, bid = blockIdx.x;
    if (bid == 192) {
        float acc = attn_b1[c];
        #pragma unroll 8
        for (int d = 0; d < DIMK; d++) acc = fmaf(pos_b2[d], attn_w1[d * NCH + c], acc);
        d_cvec[c] = acc;
        return;
    }
    int m = bid >> 6, k = bid & 63;
    const float* src = (m == 0) ? (pos_w2 + k * 64) : (m == 1) ? (w_qkv + k * 192) : (w_qkv + k * 192 + 64);
    float acc = 0.f;
    #pragma unroll 8
    for (int d = 0; d < DIMK; d++) acc = fmaf(src[d], attn_w1[d * NCH + c], acc);
    float* dst = (m == 0) ? d_M : (m == 1) ? d_Wq : d_Wk;
    dst[k * NCH + c] = acc;
}

// -------------------- K0a2: bf16 M in swizzled B layout --------------------
__global__ void prep_msplit() {
    int k = blockIdx.x, n = threadIdx.x;
    *(__nv_bfloat16*)(d_Bhi + swz(n, k)) = __float2bfloat16(d_M[k * NCH + n]);
}

// -------------------- K0b: projections --------------------
__global__ __launch_bounds__(256) void proj_kernel(const float* __restrict__ x,
                                                   const float* __restrict__ w_qkv) {
    __shared__ float xs[16][64];
    int c = threadIdx.x;
    int row0 = blockIdx.x * 16;
    for (int idx = c; idx < 16 * 64; idx += 256) xs[idx >> 6][idx & 63] = x[row0 * 64 + idx];
    __syncthreads();
    float accq[16], acck[16];
    #pragma unroll
    for (int r = 0; r < 16; r++) { accq[r] = 0.f; acck[r] = 0.f; }
    for (int k = 0; k < 64; k++) {
        float wq = d_Wq[k * NCH + c], wk = d_Wk[k * NCH + c];
        #pragma unroll
        for (int r = 0; r < 16; r++) {
            float xv = xs[r][k];
            accq[r] = fmaf(xv, wq, accq[r]);
            acck[r] = fmaf(xv, wk, acck[r]);
        }
    }
    float cv = d_cvec[c];
    #pragma unroll
    for (int r = 0; r < 16; r++) {
        d_qk1[(size_t)(row0 + r) * NCH + c] = accq[r] + cv;
        d_kk1b[(size_t)(row0 + r) * NCH + c] = __float2bfloat16(acck[r]);
    }
    int d = c & 63, rg = c >> 6;
    for (int r = rg; r < 16; r += 4) {
        float acc = 0.f;
        #pragma unroll 8
        for (int k = 0; k < 64; k++) acc = fmaf(xs[r][k], w_qkv[k * 192 + 128 + d], acc);
        d_v[(size_t)(row0 + r) * 64 + d] = acc;
    }
}

// -------------------- K1: fused attention (resident p, barrier-minimal) ---------
__global__ __launch_bounds__(NT, 1) void pt_main(const float* __restrict__ pos,
                                                 const float* __restrict__ pos_w1,
                                                 const float* __restrict__ pos_b1,
                                                 const float* __restrict__ pos_w2,
                                                 const float* __restrict__ pos_b2,
                                                 const float* __restrict__ attn_w2,
                                                 float* __restrict__ out) {
    extern __shared__ __align__(1024) char smc[];
    float* ext = (float*)(smc + OFF_EXT);
    float* pjall = ext + E_PJ; float* qs = ext + E_QS; float* w2s = ext + E_W2S;
    float* w1s = ext + E_W1S; float* b1s = ext + E_B1S; float* sims = ext + E_SIMS;
    float* spart = ext + E_SPART; float* gpart = ext + E_GPART; float* rpart = ext + E_RPART;
    float* gs = ext + E_GS; float* red = ext + E_RED;

    uint32_t sbase = smem_to_u32(smc);
    int tid = threadIdx.x, wid = tid >> 5, lane = tid & 31;
    int bi = blockIdx.x, b = bi >> 9;

    // stage B (32 KB, temporary) + block-invariant data + all pos_j
    {
        float4* dh = (float4*)smc;
        const float4* sh = (const float4*)d_Bhi;
        for (int idx = tid; idx < 2048; idx += NT) dh[idx] = sh[idx];
    }
    for (int idx = tid; idx < 1536; idx += NT) {
        int d = idx >> 9, j = idx & 511;
        pjall[d * 512 + j] = pos[((size_t)b * NSEQ + j) * 3 + d];
    }
    if (tid < 256)      { qs[tid] = d_qk1[(size_t)bi * NCH + tid]; w2s[tid] = attn_w2[tid]; }
    else if (tid < 448) { w1s[tid - 256] = pos_w1[tid - 256]; }
    else                { b1s[tid - 448] = pos_b1[tid - 448]; }
    float px = pos[bi * 3 + 0], py = pos[bi * 3 + 1], pz = pos[bi * 3 + 2];
    __syncthreads();

    // warp tiling: mg = m-group (32 rows, 4 groups), ng = n-group (64 cols, 4 groups)
    int mg = wid >> 2, ng = wid & 3;
    int m0 = mg * 32, n0base = ng * 64;
    int r8 = lane & 7, g = lane >> 3;
    int rowAoff = (g & 1) << 3, kcA = g >> 1;
    int nBoff = (g >> 1) << 3, kcB = g & 1;
    int rq = lane >> 2, t4 = lane & 3;

    // load B into registers ONCE: Breg[ch][nb][ks][4]
    uint32_t Breg[2][2][4][4];
    #pragma unroll
    for (int ch = 0; ch < 2; ch++)
        #pragma unroll
        for (int nb = 0; nb < 2; nb++)
            #pragma unroll
            for (int ks = 0; ks < 4; ks++) {
                uint32_t baddr = sbase + (n0base + ch * 32 + nb * 16 + nBoff + r8) * 128
                               + (uint32_t)(((2 * ks + kcB) ^ r8) << 4);
                ldsm4(Breg[ch][nb][ks][0], Breg[ch][nb][ks][1],
                      Breg[ch][nb][ks][2], Breg[ch][nb][ks][3], baddr);
            }
    __syncthreads();   // B smem dead; full A (64KB) reuses bytes 0..64KB

    // ---------------- p-gen for ALL 512 rows (single phase) ----------------
    for (int idx = tid; idx < 16384; idx += NT) {
        int j = idx >> 5, k = (idx & 31) << 1;
        float rx = px - pjall[j], ry = py - pjall[512 + j], rz = pz - pjall[1024 + j];
        float v0 = fmaf(rx, w1s[k],     fmaf(ry, w1s[64 + k],     fmaf(rz, w1s[128 + k],     b1s[k])));
        float v1 = fmaf(rx, w1s[k + 1], fmaf(ry, w1s[64 + k + 1], fmaf(rz, w1s[128 + k + 1], b1s[k + 1])));
        __nv_bfloat162 hh = __floats2bfloat162_rn(fmaxf(v0, 0.f), fmaxf(v1, 0.f));
        unsigned sw = j * 128 + ((((k >> 3) ^ (j & 7))) << 4) + (k & 7) * 2;
        *(uint32_t*)(smc + sw) = *(uint32_t*)&hh;
    }
    __syncthreads();

    // ---------------- PASS 1: 4 tiles back-to-back, NO barriers ----------------
    #pragma unroll 1
    for (int t = 0; t < 4; t++) {
        uint32_t Abase = sbase + (t * 128 + m0 + rowAoff + r8) * 128;
        const __nv_bfloat16* kkT = d_kk1b + ((size_t)((b << 9) + t * 128 + m0 + rq)) * NCH;
        float sm[4] = {0.f, 0.f, 0.f, 0.f};

        #pragma unroll
        for (int ch = 0; ch < 2; ch++) {
            int n0 = n0base + ch * 32;
            float acc[2][4][4];
            #pragma unroll
            for (int i = 0; i < 2; i++)
                #pragma unroll
                for (int q = 0; q < 4; q++)
                    #pragma unroll
                    for (int r = 0; r < 4; r++) acc[i][q][r] = 0.f;

            #pragma unroll
            for (int ks = 0; ks < 4; ks++) {
                uint32_t axor = (uint32_t)(((2 * ks + kcA) ^ r8) << 4);
                #pragma unroll
                for (int mb = 0; mb < 2; mb++) {
                    uint32_t ah[4];
                    ldsm4(ah[0], ah[1], ah[2], ah[3], Abase + mb * 2048 + axor);
                    #pragma unroll
                    for (int nb = 0; nb < 2; nb++) {
                        mma16816(acc[mb][2 * nb],     ah, Breg[ch][nb][ks][0], Breg[ch][nb][ks][1]);
                        mma16816(acc[mb][2 * nb + 1], ah, Breg[ch][nb][ks][2], Breg[ch][nb][ks][3]);
                    }
                }
            }
            // epilogue for this 32-col chunk
            #pragma unroll
            for (int mb = 0; mb < 2; mb++) {
                float s0 = 0.f, s1 = 0.f;
                const __nv_bfloat16* kkm = kkT + mb * 16 * NCH;
                #pragma unroll
                for (int n8 = 0; n8 < 4; n8++) {
                    int n = n0 + n8 * 8 + t4 * 2;
                    float2 qv = *(const float2*)(qs + n);
                    float2 wv = *(const float2*)(w2s + n);
                    float2 k0 = __bfloat1622float2(*(const __nv_bfloat162*)(kkm + n));
                    float2 k1 = __bfloat1622float2(*(const __nv_bfloat162*)(kkm + 8 * NCH + n));
                    s0 = fmaf(fmaxf(acc[mb][n8][0] + qv.x - k0.x, 0.f), wv.x,
                         fmaf(fmaxf(acc[mb][n8][1] + qv.y - k0.y, 0.f), wv.y, s0));
                    s1 = fmaf(fmaxf(acc[mb][n8][2] + qv.x - k1.x, 0.f), wv.x,
                         fmaf(fmaxf(acc[mb][n8][3] + qv.y - k1.y, 0.f), wv.y, s1));
                }
                sm[2 * mb] += s0; sm[2 * mb + 1] += s1;
            }
        }
        // quad reduce + write per-tile partials (disjoint slots, no barrier)
        #pragma unroll
        for (int q = 0; q < 4; q++) {
            sm[q] += __shfl_xor_sync(0xffffffffu, sm[q], 1);
            sm[q] += __shfl_xor_sync(0xffffffffu, sm[q], 2);
        }
        if (t4 == 0) {
            spart[ng * 512 + t * 128 + m0 + rq]      = sm[0];
            spart[ng * 512 + t * 128 + m0 + rq + 8]  = sm[1];
            spart[ng * 512 + t * 128 + m0 + rq + 16] = sm[2];
            spart[ng * 512 + t * 128 + m0 + rq + 24] = sm[3];
        }
    }
    __syncthreads();
    sims[tid] = spart[tid] + spart[512 + tid] + spart[1024 + tid] + spart[1536 + tid];
    __syncthreads();

    // ---------------- softmax over 512 sims ----------------
    {
        float s = sims[tid];
        float m = s;
        #pragma unroll
        for (int off = 16; off; off >>= 1) m = fmaxf(m, __shfl_xor_sync(0xffffffffu, m, off));
        if (lane == 0) red[wid] = m;
        __syncthreads();
        if (tid < 32) {
            float v = (tid < 16) ? red[tid] : -3.4e38f;
            #pragma unroll
            for (int off = 8; off; off >>= 1) v = fmaxf(v, __shfl_xor_sync(0xffffffffu, v, off));
            if (tid == 0) red[32] = v;
        }
        __syncthreads();
        float e = __expf(s - red[32]);
        float tt = e;
        #pragma unroll
        for (int off = 16; off; off >>= 1) tt += __shfl_xor_sync(0xffffffffu, tt, off);
        if (lane == 0) red[wid] = tt;
        __syncthreads();
        if (tid < 32) {
            float v = (tid < 16) ? red[tid] : 0.f;
            #pragma unroll
            for (int off = 8; off; off >>= 1) v += __shfl_xor_sync(0xffffffffu, v, off);
            if (tid == 0) red[33] = v;
        }
        __syncthreads();
        sims[tid] = e / red[33];
        __syncthreads();
    }

    // ---------------- PASS 2: per-thread p recompute; g = a@p, r = a@v ----------------
    {
        int k = tid & 63, jg = tid >> 6;     // 8 j-groups of 64 rows
        float w0 = w1s[k], w1c = w1s[64 + k], w2c = w1s[128 + k], bb = b1s[k];
        float gacc = 0.f, racc = 0.f;
        const float* vb = d_v + ((size_t)(b << 9) + jg * 64) * 64 + k;
        int j0 = jg * 64;
        #pragma unroll 4
        for (int jj = 0; jj < 64; jj++) {
            int j = j0 + jj;
            float a = sims[j];
            float rx = px - pjall[j], ry = py - pjall[512 + j], rz = pz - pjall[1024 + j];
            float pv = fmaxf(fmaf(rx, w0, fmaf(ry, w1c, fmaf(rz, w2c, bb))), 0.f);
            gacc = fmaf(a, pv, gacc);
            racc = fmaf(a, vb[jj * 64], racc);
        }
        gpart[tid] = gacc;
        rpart[tid] = racc;
        __syncthreads();
        float rsum = 0.f;
        if (tid < 64) {
            float gsum = 0.f;
            #pragma unroll
            for (int w = 0; w < 8; w++) { gsum += gpart[w * 64 + tid]; rsum += rpart[w * 64 + tid]; }
            gs[tid] = gsum;
        }
        __syncthreads();
        if (tid < 64) {
            float o = rsum + pos_b2[tid];
            #pragma unroll 8
            for (int kk = 0; kk < 64; kk++) o = fmaf(gs[kk], pos_w2[kk * 64 + tid], o);
            out[(size_t)bi * 64 + tid] = o;
        }
    }
}

// -------------------- launch --------------------
extern "C" void kernel_launch(void* const* d_in, const int* in_sizes, int n_in,
                              void* d_out, int out_size) {
    const float* x       = (const float*)d_in[0];
    const float* pos     = (const float*)d_in[1];
    const float* w_qkv   = (const float*)d_in[2];
    const float* pos_w1  = (const float*)d_in[3];
    const float* pos_b1  = (const float*)d_in[4];
    const float* pos_w2  = (const float*)d_in[5];
    const float* pos_b2  = (const float*)d_in[6];
    const float* attn_w1 = (const float*)d_in[7];
    const float* attn_b1 = (const float*)d_in[8];
    const float* attn_w2 = (const float*)d_in[9];
    // attn_b2 (d_in[10]) cancels in softmax
    float* out = (float*)d_out;

    cudaFuncSetAttribute(pt_main, cudaFuncAttributeMaxDynamicSharedMemorySize, SMEM_TOTAL);

    prep_mats<<<193, 256>>>(w_qkv, pos_w2, pos_b2, attn_w1, attn_b1);
    prep_msplit<<<64, 256>>>();
    proj_kernel<<<128, 256>>>(x, w_qkv);
    pt_main<<<NB * NSEQ, NT, SMEM_TOTAL>>>(pos, pos_w1, pos_b1, pos_w2, pos_b2, attn_w2, out);
}